// round 10
// baseline (speedup 1.0000x reference)
#include <cuda_runtime.h>
#include <cstdint>

// Problem constants (N=100000, E=3200000, D=165)
#define NMAX 100000
#define EMAX 3200000
#define D0 165
#define F1 32
#define F2 16
#define F3 2
#define CAP 128   // bucket capacity per dst; deg ~ Poisson(32), max@100k ~ 70

// Scratch (device globals — no allocation allowed). 16B-aligned for vector ops.
__device__ __align__(16) float g_buf0[NMAX * F1];   // hs1 (32 f/node)
__device__ __align__(16) float g_buf2[NMAX * F2];   // hs2 (16 f/node)
__device__ __align__(16) float g_buf1[NMAX * F3];   // hs3 (2 f/node)
__device__ __align__(16) int   g_cnt[NMAX];         // per-dst in-degree
__device__ __align__(16) int   g_bkt[(size_t)NMAX * CAP]; // src ids per dst

// ---------------------------------------------------------------------------
// Single-pass bucket fill: hist + placement fused. edge_index is int32.
// 4 edges/thread, int4 vector loads (falls back to scalar on ragged tail).
__global__ void k_fill(const int* __restrict__ ei, int E, int N) {
    int i = blockIdx.x * blockDim.x + threadIdx.x;
    int e0 = i * 4;
    if (e0 >= E) return;
    if (((E & 3) == 0) && (e0 + 4 <= E)) {
        int4 s4 = __ldg((const int4*)ei + i);
        int4 d4 = __ldg((const int4*)(ei + E) + i);
        int ss[4] = {s4.x, s4.y, s4.z, s4.w};
        int dd[4] = {d4.x, d4.y, d4.z, d4.w};
#pragma unroll
        for (int j = 0; j < 4; j++) {
            int s = ss[j], d = dd[j];
            s = (s < 0) ? 0 : ((s >= N) ? N - 1 : s);
            d = (d < 0) ? 0 : ((d >= N) ? N - 1 : d);
            int pos = atomicAdd(&g_cnt[d], 1);
            if (pos < CAP) g_bkt[(size_t)d * CAP + pos] = s;
        }
    } else {
        for (int j = 0; j < 4; j++) {
            int e = e0 + j;
            if (e >= E) return;
            int s = ei[e];
            int d = ei[E + e];
            s = (s < 0) ? 0 : ((s >= N) ? N - 1 : s);
            d = (d < 0) ? 0 : ((d >= N) ? N - 1 : d);
            int pos = atomicAdd(&g_cnt[d], 1);
            if (pos < CAP) g_bkt[(size_t)d * CAP + pos] = s;
        }
    }
}

// ---------------------------------------------------------------------------
// GEMM1: hs1 = (x @ W1) * dinv. 4 rows per warp: one LDS feeds 4 FMAs.
__global__ void k_gemm1(const float* __restrict__ x,
                        const float* __restrict__ W1, int N) {
    __shared__ float sW[D0 * F1];
    for (int i = threadIdx.x; i < D0 * F1; i += blockDim.x) sW[i] = W1[i];
    __syncthreads();

    int warp = (blockIdx.x * blockDim.x + threadIdx.x) >> 5;
    int lane = threadIdx.x & 31;
    int r0 = warp * 4;
    if (r0 >= N) return;

    float xv[4][6];
#pragma unroll
    for (int r = 0; r < 4; r++) {
        int row = r0 + r;
        if (row >= N) row = N - 1;
        const float* xr = x + (size_t)row * D0;
#pragma unroll
        for (int j = 0; j < 6; j++) {
            int idx = j * 32 + lane;
            xv[r][j] = (idx < D0) ? __ldg(xr + idx) : 0.0f;
        }
    }

    float acc[4] = {0.f, 0.f, 0.f, 0.f};
#pragma unroll
    for (int j = 0; j < 6; j++) {
#pragma unroll
        for (int t = 0; t < 32; t++) {
            int k = j * 32 + t;
            if (k >= D0) break;
            float w = sW[k * F1 + lane];
#pragma unroll
            for (int r = 0; r < 4; r++) {
                float xk = __shfl_sync(0xffffffffu, xv[r][j], t);
                acc[r] = fmaf(xk, w, acc[r]);
            }
        }
    }
#pragma unroll
    for (int r = 0; r < 4; r++) {
        int row = r0 + r;
        if (row < N) {
            float dv = rsqrtf((float)g_cnt[row] + 1.0f);
            g_buf0[(size_t)row * F1 + lane] = acc[r] * dv;
        }
    }
}

// ---------------------------------------------------------------------------
// Fused agg1 + relu + gemm2: warp per dst, lane = input feature k (0..31).
// Inner gather unrolled x8 with 8 accumulators: MLP=8, FADD chain /8.
__global__ void k_agg1g2(const float* __restrict__ W2,
                         const float* __restrict__ b1, int N) {
    __shared__ float sW[F1 * F2];
    __shared__ float sb[F1];
    for (int i = threadIdx.x; i < F1 * F2; i += blockDim.x) sW[i] = W2[i];
    if (threadIdx.x < F1) sb[threadIdx.x] = b1[threadIdx.x];
    __syncthreads();

    int d = (blockIdx.x * blockDim.x + threadIdx.x) >> 5;
    int lane = threadIdx.x & 31;
    if (d >= N) return;

    int cnt = g_cnt[d];
    float dv = rsqrtf((float)cnt + 1.0f);
    if (cnt > CAP) cnt = CAP;
    const int* row = g_bkt + (size_t)d * CAP;
    const float* bufl = g_buf0 + lane;

    float a0 = g_buf0[(size_t)d * F1 + lane];   // self term
    float a1 = 0.f, a2 = 0.f, a3 = 0.f;
    float a4 = 0.f, a5 = 0.f, a6 = 0.f, a7 = 0.f;
    int base = 0;
    while (base < cnt) {
        int m = min(32, cnt - base);
        int sid = (lane < m) ? __ldg(row + base + lane) : 0;
        int t = 0;
        for (; t + 8 <= m; t += 8) {
            int s0 = __shfl_sync(0xffffffffu, sid, t);
            int s1 = __shfl_sync(0xffffffffu, sid, t + 1);
            int s2 = __shfl_sync(0xffffffffu, sid, t + 2);
            int s3 = __shfl_sync(0xffffffffu, sid, t + 3);
            int s4 = __shfl_sync(0xffffffffu, sid, t + 4);
            int s5 = __shfl_sync(0xffffffffu, sid, t + 5);
            int s6 = __shfl_sync(0xffffffffu, sid, t + 6);
            int s7 = __shfl_sync(0xffffffffu, sid, t + 7);
            float v0 = __ldg(bufl + (size_t)s0 * F1);
            float v1 = __ldg(bufl + (size_t)s1 * F1);
            float v2 = __ldg(bufl + (size_t)s2 * F1);
            float v3 = __ldg(bufl + (size_t)s3 * F1);
            float v4 = __ldg(bufl + (size_t)s4 * F1);
            float v5 = __ldg(bufl + (size_t)s5 * F1);
            float v6 = __ldg(bufl + (size_t)s6 * F1);
            float v7 = __ldg(bufl + (size_t)s7 * F1);
            a0 += v0; a1 += v1; a2 += v2; a3 += v3;
            a4 += v4; a5 += v5; a6 += v6; a7 += v7;
        }
        for (; t + 2 <= m; t += 2) {
            int s0 = __shfl_sync(0xffffffffu, sid, t);
            int s1 = __shfl_sync(0xffffffffu, sid, t + 1);
            float v0 = __ldg(bufl + (size_t)s0 * F1);
            float v1 = __ldg(bufl + (size_t)s1 * F1);
            a0 += v0; a1 += v1;
        }
        for (; t < m; t++) {
            int s = __shfl_sync(0xffffffffu, sid, t);
            a0 += __ldg(bufl + (size_t)s * F1);
        }
        base += 32;
    }
    float acc = ((a0 + a1) + (a2 + a3)) + ((a4 + a5) + (a6 + a7));
    float in = fmaxf(fmaf(acc, dv, sb[lane]), 0.0f);

    // gemm2: lanes 0-15 cover k=0..15, lanes 16-31 cover k=16..31; f = lane&15
    int f = lane & 15;
    int kbase = lane & 16;
    float o = 0.0f;
#pragma unroll
    for (int t = 0; t < 16; t++) {
        int k = kbase + t;
        float xk = __shfl_sync(0xffffffffu, in, k);
        o = fmaf(xk, sW[k * F2 + f], o);
    }
    o += __shfl_xor_sync(0xffffffffu, o, 16);
    if (lane < 16) g_buf2[(size_t)d * F2 + f] = o * dv;
}

// ---------------------------------------------------------------------------
// Fused agg2 + relu + gemm3: 16-thread group per dst, f = feature (0..15).
// Half-warp segment masks; gather unrolled x8 with 8 accumulators.
__global__ void k_agg2g3(const float* __restrict__ W3,
                         const float* __restrict__ b2, int N) {
    __shared__ float sW[F2 * F3];
    __shared__ float sb[F2];
    if (threadIdx.x < F2 * F3) sW[threadIdx.x] = W3[threadIdx.x];
    if (threadIdx.x < F2) sb[threadIdx.x] = b2[threadIdx.x];
    __syncthreads();

    int d = (blockIdx.x * blockDim.x + threadIdx.x) >> 4;
    int f = threadIdx.x & 15;
    unsigned hmask = 0xFFFFu << (threadIdx.x & 16);
    if (d >= N) return;

    int cnt = g_cnt[d];
    float dv = rsqrtf((float)cnt + 1.0f);
    if (cnt > CAP) cnt = CAP;
    const int* row = g_bkt + (size_t)d * CAP;
    const float* bufl = g_buf2 + f;

    float a0 = g_buf2[(size_t)d * F2 + f];   // self term
    float a1 = 0.f, a2 = 0.f, a3 = 0.f;
    float a4 = 0.f, a5 = 0.f, a6 = 0.f, a7 = 0.f;
    int base = 0;
    while (base < cnt) {
        int m = min(16, cnt - base);
        int sid = (f < m) ? __ldg(row + base + f) : 0;
        int t = 0;
        for (; t + 8 <= m; t += 8) {
            int s0 = __shfl_sync(hmask, sid, t, 16);
            int s1 = __shfl_sync(hmask, sid, t + 1, 16);
            int s2 = __shfl_sync(hmask, sid, t + 2, 16);
            int s3 = __shfl_sync(hmask, sid, t + 3, 16);
            int s4 = __shfl_sync(hmask, sid, t + 4, 16);
            int s5 = __shfl_sync(hmask, sid, t + 5, 16);
            int s6 = __shfl_sync(hmask, sid, t + 6, 16);
            int s7 = __shfl_sync(hmask, sid, t + 7, 16);
            float v0 = __ldg(bufl + (size_t)s0 * F2);
            float v1 = __ldg(bufl + (size_t)s1 * F2);
            float v2 = __ldg(bufl + (size_t)s2 * F2);
            float v3 = __ldg(bufl + (size_t)s3 * F2);
            float v4 = __ldg(bufl + (size_t)s4 * F2);
            float v5 = __ldg(bufl + (size_t)s5 * F2);
            float v6 = __ldg(bufl + (size_t)s6 * F2);
            float v7 = __ldg(bufl + (size_t)s7 * F2);
            a0 += v0; a1 += v1; a2 += v2; a3 += v3;
            a4 += v4; a5 += v5; a6 += v6; a7 += v7;
        }
        for (; t < m; t++) {
            int s = __shfl_sync(hmask, sid, t, 16);
            a0 += __ldg(bufl + (size_t)s * F2);
        }
        base += 16;
    }
    float acc = ((a0 + a1) + (a2 + a3)) + ((a4 + a5) + (a6 + a7));
    float in = fmaxf(fmaf(acc, dv, sb[f]), 0.0f);

    // gemm3: per-lane partials, reduce across the 16-group
    float p0 = in * sW[f * F3 + 0];
    float p1 = in * sW[f * F3 + 1];
#pragma unroll
    for (int off = 8; off; off >>= 1) {
        p0 += __shfl_xor_sync(hmask, p0, off, 16);
        p1 += __shfl_xor_sync(hmask, p1, off, 16);
    }
    if (f == 0) {
        g_buf1[(size_t)d * F3 + 0] = p0 * dv;
        g_buf1[(size_t)d * F3 + 1] = p1 * dv;
    }
}

// ---------------------------------------------------------------------------
// Aggregation layer 3 + bias + log_softmax (fused).
// Warp per dst; lane handles edge (lane>>1), feature (lane&1).
__global__ void k_agg3(const float* __restrict__ b3,
                       float* __restrict__ out, int N) {
    int d = (blockIdx.x * blockDim.x + threadIdx.x) >> 5;
    int lane = threadIdx.x & 31;
    if (d >= N) return;
    int e2 = lane >> 1;
    int f = lane & 1;
    int cnt = g_cnt[d];
    float dv = rsqrtf((float)cnt + 1.0f);
    if (cnt > CAP) cnt = CAP;
    const int* row = g_bkt + (size_t)d * CAP;
    float acc = 0.0f;
    int base = 0;
    while (base < cnt) {
        int m = min(16, cnt - base);
        int sid = (lane < m) ? __ldg(row + base + lane) : 0;
        int s = __shfl_sync(0xffffffffu, sid, e2);
        if (e2 < m) acc += __ldg(g_buf1 + (size_t)s * F3 + f);
        base += 16;
    }
    // self term, added once per feature (lanes 0 and 1 only)
    if (lane < 2) acc += g_buf1[(size_t)d * F3 + lane];
#pragma unroll
    for (int off = 2; off < 32; off <<= 1)
        acc += __shfl_xor_sync(0xffffffffu, acc, off);
    float a = fmaf(acc, dv, __ldg(b3 + f));
    float o = __shfl_xor_sync(0xffffffffu, a, 1);
    if (lane < 2) {
        float m = fmaxf(a, o);
        float l = m + logf(expf(a - m) + expf(o - m));
        out[(size_t)d * 2 + lane] = a - l;
    }
}

// ---------------------------------------------------------------------------
extern "C" void kernel_launch(void* const* d_in, const int* in_sizes, int n_in,
                              void* d_out, int out_size) {
    const float* x  = (const float*)d_in[0];
    const int*   ei = (const int*)d_in[1];
    const float* W1 = (const float*)d_in[2];
    const float* b1 = (const float*)d_in[3];
    const float* W2 = (const float*)d_in[4];
    const float* b2 = (const float*)d_in[5];
    const float* W3 = (const float*)d_in[6];
    const float* b3 = (const float*)d_in[7];
    float* out      = (float*)d_out;

    int N = in_sizes[0] / D0;
    int E = in_sizes[1] / 2;
    if (N > NMAX) N = NMAX;
    if (E > EMAX) E = EMAX;

    // Zero degree counters via async memset (capturable, saves a launch)
    void* cnt_ptr = nullptr;
    cudaGetSymbolAddress(&cnt_ptr, g_cnt);
    cudaMemsetAsync(cnt_ptr, 0, (size_t)N * sizeof(int));

    // Bucket-CSR build (one edge-list pass)
    k_fill<<<(E / 4 + 255) / 256, 256>>>(ei, E, N);

    // Layer 1 GEMM, then fused layers
    k_gemm1<<<(((N + 3) / 4) * 32 + 255) / 256, 256>>>(x, W1, N);
    k_agg1g2<<<(N * 32 + 255) / 256, 256>>>(W2, b1, N);
    k_agg2g3<<<(N * 16 + 255) / 256, 256>>>(W3, b2, N);
    k_agg3<<<(N * 32 + 255) / 256, 256>>>(b3, out, N);
}

// round 11
// speedup vs baseline: 1.0808x; 1.0808x over previous
#include <cuda_runtime.h>
#include <cstdint>

// Problem constants (N=100000, E=3200000, D=165)
#define NMAX 100000
#define EMAX 3200000
#define D0 165
#define F1 32
#define F2 16
#define F3 2
#define CAP 128   // bucket capacity per dst; deg ~ Poisson(32), max@100k ~ 70

// Scratch (device globals — no allocation allowed). 16B-aligned for vector ops.
__device__ __align__(16) float g_buf0[NMAX * F1];   // hs1 (32 f/node)
__device__ __align__(16) float g_buf2[NMAX * F2];   // hs2 (16 f/node)
__device__ __align__(16) float g_buf1[NMAX * F3];   // hs3 (2 f/node)
__device__ __align__(16) int   g_cnt[NMAX];         // per-dst in-degree
__device__ __align__(16) int   g_bkt[(size_t)NMAX * CAP]; // src ids per dst

// ---------------------------------------------------------------------------
// Fused fill + gemm1. Even/odd block interleave co-schedules the two
// independent workloads on every SM: fill is atomic-latency-bound (low issue),
// gemm1 is issue-bound — they overlap. gemm1 here writes UNSCALED h (dinv is
// applied by k_scale afterwards, since g_cnt is still being built here).
__device__ __forceinline__ void fill_body(const int* __restrict__ ei,
                                          int blk, int E, int N) {
    int i = blk * 256 + threadIdx.x;
    int e0 = i * 4;
    if (e0 >= E) return;
    if (((E & 3) == 0) && (e0 + 4 <= E)) {
        int4 s4 = __ldg((const int4*)ei + i);
        int4 d4 = __ldg((const int4*)(ei + E) + i);
        int ss[4] = {s4.x, s4.y, s4.z, s4.w};
        int dd[4] = {d4.x, d4.y, d4.z, d4.w};
#pragma unroll
        for (int j = 0; j < 4; j++) {
            int s = ss[j], d = dd[j];
            s = (s < 0) ? 0 : ((s >= N) ? N - 1 : s);
            d = (d < 0) ? 0 : ((d >= N) ? N - 1 : d);
            int pos = atomicAdd(&g_cnt[d], 1);
            if (pos < CAP) g_bkt[(size_t)d * CAP + pos] = s;
        }
    } else {
        for (int j = 0; j < 4; j++) {
            int e = e0 + j;
            if (e >= E) return;
            int s = ei[e];
            int d = ei[E + e];
            s = (s < 0) ? 0 : ((s >= N) ? N - 1 : s);
            d = (d < 0) ? 0 : ((d >= N) ? N - 1 : d);
            int pos = atomicAdd(&g_cnt[d], 1);
            if (pos < CAP) g_bkt[(size_t)d * CAP + pos] = s;
        }
    }
}

__device__ __forceinline__ void gemm1_body(const float* __restrict__ x,
                                           const float* sW,
                                           int blk, int N) {
    int warp = (blk * 256 + threadIdx.x) >> 5;
    int lane = threadIdx.x & 31;
    int r0 = warp * 4;
    if (r0 >= N) return;

    float xv[4][6];
#pragma unroll
    for (int r = 0; r < 4; r++) {
        int row = r0 + r;
        if (row >= N) row = N - 1;
        const float* xr = x + (size_t)row * D0;
#pragma unroll
        for (int j = 0; j < 6; j++) {
            int idx = j * 32 + lane;
            xv[r][j] = (idx < D0) ? __ldg(xr + idx) : 0.0f;
        }
    }

    float acc[4] = {0.f, 0.f, 0.f, 0.f};
#pragma unroll
    for (int j = 0; j < 6; j++) {
#pragma unroll
        for (int t = 0; t < 32; t++) {
            int k = j * 32 + t;
            if (k >= D0) break;
            float w = sW[k * F1 + lane];
#pragma unroll
            for (int r = 0; r < 4; r++) {
                float xk = __shfl_sync(0xffffffffu, xv[r][j], t);
                acc[r] = fmaf(xk, w, acc[r]);
            }
        }
    }
#pragma unroll
    for (int r = 0; r < 4; r++) {
        int row = r0 + r;
        if (row < N) g_buf0[(size_t)row * F1 + lane] = acc[r];  // unscaled
    }
}

__global__ void k_fill_gemm1(const int* __restrict__ ei,
                             const float* __restrict__ x,
                             const float* __restrict__ W1,
                             int E, int N, int gb, int fb) {
    __shared__ float sW[D0 * F1];
    for (int i = threadIdx.x; i < D0 * F1; i += blockDim.x) sW[i] = W1[i];
    __syncthreads();

    int bid = blockIdx.x;
    int half = (gb < fb) ? gb : fb;
    if (bid < 2 * half) {
        if (bid & 1) fill_body(ei, bid >> 1, E, N);
        else         gemm1_body(x, sW, bid >> 1, N);
    } else {
        int r = bid - 2 * half;
        if (gb > fb) gemm1_body(x, sW, half + r, N);
        else         fill_body(ei, half + r, E, N);
    }
}

// Apply dinv scaling to hs1 (warp reads one cnt, broadcast across 32 lanes).
__global__ void k_scale(int N) {
    int i = blockIdx.x * blockDim.x + threadIdx.x;
    if (i >= N * F1) return;
    int row = i >> 5;
    float dv = rsqrtf((float)__ldg(g_cnt + row) + 1.0f);
    g_buf0[i] *= dv;
}

// ---------------------------------------------------------------------------
// Fused agg1 + relu + gemm2: warp per dst, lane = input feature k (0..31).
// Inner gather unrolled x4 with 4 accumulators (R8 config: 32 regs, occ 83%).
__global__ void k_agg1g2(const float* __restrict__ W2,
                         const float* __restrict__ b1, int N) {
    __shared__ float sW[F1 * F2];
    __shared__ float sb[F1];
    for (int i = threadIdx.x; i < F1 * F2; i += blockDim.x) sW[i] = W2[i];
    if (threadIdx.x < F1) sb[threadIdx.x] = b1[threadIdx.x];
    __syncthreads();

    int d = (blockIdx.x * blockDim.x + threadIdx.x) >> 5;
    int lane = threadIdx.x & 31;
    if (d >= N) return;

    int cnt = g_cnt[d];
    float dv = rsqrtf((float)cnt + 1.0f);
    if (cnt > CAP) cnt = CAP;
    const int* row = g_bkt + (size_t)d * CAP;
    const float* bufl = g_buf0 + lane;

    float a0 = g_buf0[(size_t)d * F1 + lane];   // self term
    float a1 = 0.f, a2 = 0.f, a3 = 0.f;
    int base = 0;
    while (base < cnt) {
        int m = min(32, cnt - base);
        int sid = (lane < m) ? __ldg(row + base + lane) : 0;
        int t = 0;
        for (; t + 4 <= m; t += 4) {
            int s0 = __shfl_sync(0xffffffffu, sid, t);
            int s1 = __shfl_sync(0xffffffffu, sid, t + 1);
            int s2 = __shfl_sync(0xffffffffu, sid, t + 2);
            int s3 = __shfl_sync(0xffffffffu, sid, t + 3);
            float v0 = __ldg(bufl + (size_t)s0 * F1);
            float v1 = __ldg(bufl + (size_t)s1 * F1);
            float v2 = __ldg(bufl + (size_t)s2 * F1);
            float v3 = __ldg(bufl + (size_t)s3 * F1);
            a0 += v0; a1 += v1; a2 += v2; a3 += v3;
        }
        for (; t < m; t++) {
            int s = __shfl_sync(0xffffffffu, sid, t);
            a0 += __ldg(bufl + (size_t)s * F1);
        }
        base += 32;
    }
    float acc = (a0 + a1) + (a2 + a3);
    float in = fmaxf(fmaf(acc, dv, sb[lane]), 0.0f);

    // gemm2: lanes 0-15 cover k=0..15, lanes 16-31 cover k=16..31; f = lane&15
    int f = lane & 15;
    int kbase = lane & 16;
    float o = 0.0f;
#pragma unroll
    for (int t = 0; t < 16; t++) {
        int k = kbase + t;
        float xk = __shfl_sync(0xffffffffu, in, k);
        o = fmaf(xk, sW[k * F2 + f], o);
    }
    o += __shfl_xor_sync(0xffffffffu, o, 16);
    if (lane < 16) g_buf2[(size_t)d * F2 + f] = o * dv;
}

// ---------------------------------------------------------------------------
// Fused agg2 + relu + gemm3: 16-thread group per dst, f = feature (0..15).
// Half-warp segment masks; gather unrolled x4 (R8 config).
__global__ void k_agg2g3(const float* __restrict__ W3,
                         const float* __restrict__ b2, int N) {
    __shared__ float sW[F2 * F3];
    __shared__ float sb[F2];
    if (threadIdx.x < F2 * F3) sW[threadIdx.x] = W3[threadIdx.x];
    if (threadIdx.x < F2) sb[threadIdx.x] = b2[threadIdx.x];
    __syncthreads();

    int d = (blockIdx.x * blockDim.x + threadIdx.x) >> 4;
    int f = threadIdx.x & 15;
    unsigned hmask = 0xFFFFu << (threadIdx.x & 16);
    if (d >= N) return;

    int cnt = g_cnt[d];
    float dv = rsqrtf((float)cnt + 1.0f);
    if (cnt > CAP) cnt = CAP;
    const int* row = g_bkt + (size_t)d * CAP;
    const float* bufl = g_buf2 + f;

    float a0 = g_buf2[(size_t)d * F2 + f];   // self term
    float a1 = 0.f, a2 = 0.f, a3 = 0.f;
    int base = 0;
    while (base < cnt) {
        int m = min(16, cnt - base);
        int sid = (f < m) ? __ldg(row + base + f) : 0;
        int t = 0;
        for (; t + 4 <= m; t += 4) {
            int s0 = __shfl_sync(hmask, sid, t, 16);
            int s1 = __shfl_sync(hmask, sid, t + 1, 16);
            int s2 = __shfl_sync(hmask, sid, t + 2, 16);
            int s3 = __shfl_sync(hmask, sid, t + 3, 16);
            float v0 = __ldg(bufl + (size_t)s0 * F2);
            float v1 = __ldg(bufl + (size_t)s1 * F2);
            float v2 = __ldg(bufl + (size_t)s2 * F2);
            float v3 = __ldg(bufl + (size_t)s3 * F2);
            a0 += v0; a1 += v1; a2 += v2; a3 += v3;
        }
        for (; t < m; t++) {
            int s = __shfl_sync(hmask, sid, t, 16);
            a0 += __ldg(bufl + (size_t)s * F2);
        }
        base += 16;
    }
    float acc = (a0 + a1) + (a2 + a3);
    float in = fmaxf(fmaf(acc, dv, sb[f]), 0.0f);

    // gemm3: per-lane partials, reduce across the 16-group
    float p0 = in * sW[f * F3 + 0];
    float p1 = in * sW[f * F3 + 1];
#pragma unroll
    for (int off = 8; off; off >>= 1) {
        p0 += __shfl_xor_sync(hmask, p0, off, 16);
        p1 += __shfl_xor_sync(hmask, p1, off, 16);
    }
    if (f == 0) {
        g_buf1[(size_t)d * F3 + 0] = p0 * dv;
        g_buf1[(size_t)d * F3 + 1] = p1 * dv;
    }
}

// ---------------------------------------------------------------------------
// Aggregation layer 3 + bias + log_softmax (fused).
// Warp per dst; lane handles edge (lane>>1), feature (lane&1).
__global__ void k_agg3(const float* __restrict__ b3,
                       float* __restrict__ out, int N) {
    int d = (blockIdx.x * blockDim.x + threadIdx.x) >> 5;
    int lane = threadIdx.x & 31;
    if (d >= N) return;
    int e2 = lane >> 1;
    int f = lane & 1;
    int cnt = g_cnt[d];
    float dv = rsqrtf((float)cnt + 1.0f);
    if (cnt > CAP) cnt = CAP;
    const int* row = g_bkt + (size_t)d * CAP;
    float acc = 0.0f;
    int base = 0;
    while (base < cnt) {
        int m = min(16, cnt - base);
        int sid = (lane < m) ? __ldg(row + base + lane) : 0;
        int s = __shfl_sync(0xffffffffu, sid, e2);
        if (e2 < m) acc += __ldg(g_buf1 + (size_t)s * F3 + f);
        base += 16;
    }
    // self term, added once per feature (lanes 0 and 1 only)
    if (lane < 2) acc += g_buf1[(size_t)d * F3 + lane];
#pragma unroll
    for (int off = 2; off < 32; off <<= 1)
        acc += __shfl_xor_sync(0xffffffffu, acc, off);
    float a = fmaf(acc, dv, __ldg(b3 + f));
    float o = __shfl_xor_sync(0xffffffffu, a, 1);
    if (lane < 2) {
        float m = fmaxf(a, o);
        float l = m + logf(expf(a - m) + expf(o - m));
        out[(size_t)d * 2 + lane] = a - l;
    }
}

// ---------------------------------------------------------------------------
extern "C" void kernel_launch(void* const* d_in, const int* in_sizes, int n_in,
                              void* d_out, int out_size) {
    const float* x  = (const float*)d_in[0];
    const int*   ei = (const int*)d_in[1];
    const float* W1 = (const float*)d_in[2];
    const float* b1 = (const float*)d_in[3];
    const float* W2 = (const float*)d_in[4];
    const float* b2 = (const float*)d_in[5];
    const float* W3 = (const float*)d_in[6];
    const float* b3 = (const float*)d_in[7];
    float* out      = (float*)d_out;

    int N = in_sizes[0] / D0;
    int E = in_sizes[1] / 2;
    if (N > NMAX) N = NMAX;
    if (E > EMAX) E = EMAX;

    // Zero degree counters via async memset (capturable)
    void* cnt_ptr = nullptr;
    cudaGetSymbolAddress(&cnt_ptr, g_cnt);
    cudaMemsetAsync(cnt_ptr, 0, (size_t)N * sizeof(int));

    // Fused fill + gemm1 (independent workloads co-scheduled), then dinv scale
    int gb = (((N + 3) / 4) * 32 + 255) / 256;   // gemm1 blocks
    int fb = (E / 4 + 255) / 256;                // fill blocks
    k_fill_gemm1<<<gb + fb, 256>>>(ei, x, W1, E, N, gb, fb);
    k_scale<<<(N * F1 + 255) / 256, 256>>>(N);

    // Fused layers
    k_agg1g2<<<(N * 32 + 255) / 256, 256>>>(W2, b1, N);
    k_agg2g3<<<(N * 16 + 255) / 256, 256>>>(W3, b2, N);
    k_agg3<<<(N * 32 + 255) / 256, 256>>>(b3, out, N);
}

// round 12
// speedup vs baseline: 1.0964x; 1.0145x over previous
#include <cuda_runtime.h>
#include <cuda_fp16.h>
#include <cstdint>

// Problem constants (N=100000, E=3200000, D=165)
#define NMAX 100000
#define EMAX 3200000
#define D0 165
#define F1 32
#define F2 16
#define F3 2
#define CAP 128   // bucket capacity per dst; deg ~ Poisson(32), max@100k ~ 70

// Scratch (device globals — no allocation allowed). 16B-aligned for vector ops.
__device__ __align__(16) __half g_buf0[NMAX * F1];  // hs1 (32 f/node, fp16, 64B rows)
__device__ __align__(16) float g_buf2[NMAX * F2];   // hs2 (16 f/node, fp32)
__device__ __align__(16) float g_buf1[NMAX * F3];   // hs3 (2 f/node, fp32)
__device__ __align__(16) int   g_cnt[NMAX];         // per-dst in-degree
__device__ __align__(16) int   g_bkt[(size_t)NMAX * CAP]; // src ids per dst

// ---------------------------------------------------------------------------
// Fused fill + gemm1 (independent workloads co-scheduled via even/odd block
// interleave). gemm1 writes UNSCALED h in fp16; k_scale applies dinv after
// g_cnt is complete.
__device__ __forceinline__ void fill_body(const int* __restrict__ ei,
                                          int blk, int E, int N) {
    int i = blk * 256 + threadIdx.x;
    int e0 = i * 4;
    if (e0 >= E) return;
    if (((E & 3) == 0) && (e0 + 4 <= E)) {
        int4 s4 = __ldg((const int4*)ei + i);
        int4 d4 = __ldg((const int4*)(ei + E) + i);
        int ss[4] = {s4.x, s4.y, s4.z, s4.w};
        int dd[4] = {d4.x, d4.y, d4.z, d4.w};
#pragma unroll
        for (int j = 0; j < 4; j++) {
            int s = ss[j], d = dd[j];
            s = (s < 0) ? 0 : ((s >= N) ? N - 1 : s);
            d = (d < 0) ? 0 : ((d >= N) ? N - 1 : d);
            int pos = atomicAdd(&g_cnt[d], 1);
            if (pos < CAP) g_bkt[(size_t)d * CAP + pos] = s;
        }
    } else {
        for (int j = 0; j < 4; j++) {
            int e = e0 + j;
            if (e >= E) return;
            int s = ei[e];
            int d = ei[E + e];
            s = (s < 0) ? 0 : ((s >= N) ? N - 1 : s);
            d = (d < 0) ? 0 : ((d >= N) ? N - 1 : d);
            int pos = atomicAdd(&g_cnt[d], 1);
            if (pos < CAP) g_bkt[(size_t)d * CAP + pos] = s;
        }
    }
}

__device__ __forceinline__ void gemm1_body(const float* __restrict__ x,
                                           const float* sW,
                                           int blk, int N) {
    int warp = (blk * 256 + threadIdx.x) >> 5;
    int lane = threadIdx.x & 31;
    int r0 = warp * 4;
    if (r0 >= N) return;

    float xv[4][6];
#pragma unroll
    for (int r = 0; r < 4; r++) {
        int row = r0 + r;
        if (row >= N) row = N - 1;
        const float* xr = x + (size_t)row * D0;
#pragma unroll
        for (int j = 0; j < 6; j++) {
            int idx = j * 32 + lane;
            xv[r][j] = (idx < D0) ? __ldg(xr + idx) : 0.0f;
        }
    }

    float acc[4] = {0.f, 0.f, 0.f, 0.f};
#pragma unroll
    for (int j = 0; j < 6; j++) {
#pragma unroll
        for (int t = 0; t < 32; t++) {
            int k = j * 32 + t;
            if (k >= D0) break;
            float w = sW[k * F1 + lane];
#pragma unroll
            for (int r = 0; r < 4; r++) {
                float xk = __shfl_sync(0xffffffffu, xv[r][j], t);
                acc[r] = fmaf(xk, w, acc[r]);
            }
        }
    }
#pragma unroll
    for (int r = 0; r < 4; r++) {
        int row = r0 + r;
        if (row < N) g_buf0[(size_t)row * F1 + lane] = __float2half(acc[r]);
    }
}

__global__ void k_fill_gemm1(const int* __restrict__ ei,
                             const float* __restrict__ x,
                             const float* __restrict__ W1,
                             int E, int N, int gb, int fb) {
    __shared__ float sW[D0 * F1];
    for (int i = threadIdx.x; i < D0 * F1; i += blockDim.x) sW[i] = W1[i];
    __syncthreads();

    int bid = blockIdx.x;
    int half = (gb < fb) ? gb : fb;
    if (bid < 2 * half) {
        if (bid & 1) fill_body(ei, bid >> 1, E, N);
        else         gemm1_body(x, sW, bid >> 1, N);
    } else {
        int r = bid - 2 * half;
        if (gb > fb) gemm1_body(x, sW, half + r, N);
        else         fill_body(ei, half + r, E, N);
    }
}

// Apply dinv scaling to hs1 (half2 pairs; 16 half2 per node row).
__global__ void k_scale(int N) {
    int i = blockIdx.x * blockDim.x + threadIdx.x;
    if (i >= N * (F1 / 2)) return;
    int row = i >> 4;
    float dv = rsqrtf((float)__ldg(g_cnt + row) + 1.0f);
    __half2* p = (__half2*)g_buf0 + i;
    float2 f = __half22float2(*p);
    *p = __floats2half2_rn(f.x * dv, f.y * dv);
}

// ---------------------------------------------------------------------------
// Fused agg1 + relu + gemm2: warp per dst, lane = input feature k (0..31).
// Gather of fp16 hs1 (64B rows), x4 unroll, sid chunk prefetch pipeline.
__global__ void k_agg1g2(const float* __restrict__ W2,
                         const float* __restrict__ b1, int N) {
    __shared__ float sW[F1 * F2];
    __shared__ float sb[F1];
    for (int i = threadIdx.x; i < F1 * F2; i += blockDim.x) sW[i] = W2[i];
    if (threadIdx.x < F1) sb[threadIdx.x] = b1[threadIdx.x];
    __syncthreads();

    int d = (blockIdx.x * blockDim.x + threadIdx.x) >> 5;
    int lane = threadIdx.x & 31;
    if (d >= N) return;

    int cnt = g_cnt[d];
    float dv = rsqrtf((float)cnt + 1.0f);
    if (cnt > CAP) cnt = CAP;
    const int* row = g_bkt + (size_t)d * CAP;
    const __half* bufl = g_buf0 + lane;

    float a0 = __half2float(g_buf0[(size_t)d * F1 + lane]);   // self term
    float a1 = 0.f, a2 = 0.f, a3 = 0.f;

    int sid = (lane < cnt) ? __ldg(row + lane) : 0;   // chunk 0 sids
    int base = 0;
    while (base < cnt) {
        int m = min(32, cnt - base);
        int nbase = base + 32;
        int nsid = 0;
        if (nbase + lane < cnt) nsid = __ldg(row + nbase + lane);  // prefetch
        int t = 0;
        for (; t + 4 <= m; t += 4) {
            int s0 = __shfl_sync(0xffffffffu, sid, t);
            int s1 = __shfl_sync(0xffffffffu, sid, t + 1);
            int s2 = __shfl_sync(0xffffffffu, sid, t + 2);
            int s3 = __shfl_sync(0xffffffffu, sid, t + 3);
            float v0 = __half2float(__ldg(bufl + (size_t)s0 * F1));
            float v1 = __half2float(__ldg(bufl + (size_t)s1 * F1));
            float v2 = __half2float(__ldg(bufl + (size_t)s2 * F1));
            float v3 = __half2float(__ldg(bufl + (size_t)s3 * F1));
            a0 += v0; a1 += v1; a2 += v2; a3 += v3;
        }
        for (; t < m; t++) {
            int s = __shfl_sync(0xffffffffu, sid, t);
            a0 += __half2float(__ldg(bufl + (size_t)s * F1));
        }
        sid = nsid;
        base = nbase;
    }
    float acc = (a0 + a1) + (a2 + a3);
    float in = fmaxf(fmaf(acc, dv, sb[lane]), 0.0f);

    // gemm2: lanes 0-15 cover k=0..15, lanes 16-31 cover k=16..31; f = lane&15
    int f = lane & 15;
    int kbase = lane & 16;
    float o = 0.0f;
#pragma unroll
    for (int t = 0; t < 16; t++) {
        int k = kbase + t;
        float xk = __shfl_sync(0xffffffffu, in, k);
        o = fmaf(xk, sW[k * F2 + f], o);
    }
    o += __shfl_xor_sync(0xffffffffu, o, 16);
    if (lane < 16) g_buf2[(size_t)d * F2 + f] = o * dv;
}

// ---------------------------------------------------------------------------
// Fused agg2 + relu + gemm3: 16-thread group per dst, f = feature (0..15).
// Half-warp segment masks; gather unrolled x4 (R8 config, fp32 hs2).
__global__ void k_agg2g3(const float* __restrict__ W3,
                         const float* __restrict__ b2, int N) {
    __shared__ float sW[F2 * F3];
    __shared__ float sb[F2];
    if (threadIdx.x < F2 * F3) sW[threadIdx.x] = W3[threadIdx.x];
    if (threadIdx.x < F2) sb[threadIdx.x] = b2[threadIdx.x];
    __syncthreads();

    int d = (blockIdx.x * blockDim.x + threadIdx.x) >> 4;
    int f = threadIdx.x & 15;
    unsigned hmask = 0xFFFFu << (threadIdx.x & 16);
    if (d >= N) return;

    int cnt = g_cnt[d];
    float dv = rsqrtf((float)cnt + 1.0f);
    if (cnt > CAP) cnt = CAP;
    const int* row = g_bkt + (size_t)d * CAP;
    const float* bufl = g_buf2 + f;

    float a0 = g_buf2[(size_t)d * F2 + f];   // self term
    float a1 = 0.f, a2 = 0.f, a3 = 0.f;
    int base = 0;
    while (base < cnt) {
        int m = min(16, cnt - base);
        int sid = (f < m) ? __ldg(row + base + f) : 0;
        int t = 0;
        for (; t + 4 <= m; t += 4) {
            int s0 = __shfl_sync(hmask, sid, t, 16);
            int s1 = __shfl_sync(hmask, sid, t + 1, 16);
            int s2 = __shfl_sync(hmask, sid, t + 2, 16);
            int s3 = __shfl_sync(hmask, sid, t + 3, 16);
            float v0 = __ldg(bufl + (size_t)s0 * F2);
            float v1 = __ldg(bufl + (size_t)s1 * F2);
            float v2 = __ldg(bufl + (size_t)s2 * F2);
            float v3 = __ldg(bufl + (size_t)s3 * F2);
            a0 += v0; a1 += v1; a2 += v2; a3 += v3;
        }
        for (; t < m; t++) {
            int s = __shfl_sync(hmask, sid, t, 16);
            a0 += __ldg(bufl + (size_t)s * F2);
        }
        base += 16;
    }
    float acc = (a0 + a1) + (a2 + a3);
    float in = fmaxf(fmaf(acc, dv, sb[f]), 0.0f);

    // gemm3: per-lane partials, reduce across the 16-group
    float p0 = in * sW[f * F3 + 0];
    float p1 = in * sW[f * F3 + 1];
#pragma unroll
    for (int off = 8; off; off >>= 1) {
        p0 += __shfl_xor_sync(hmask, p0, off, 16);
        p1 += __shfl_xor_sync(hmask, p1, off, 16);
    }
    if (f == 0) {
        g_buf1[(size_t)d * F3 + 0] = p0 * dv;
        g_buf1[(size_t)d * F3 + 1] = p1 * dv;
    }
}

// ---------------------------------------------------------------------------
// Aggregation layer 3 + bias + log_softmax (fused).
// Warp per dst; lane handles edge (lane>>1), feature (lane&1).
__global__ void k_agg3(const float* __restrict__ b3,
                       float* __restrict__ out, int N) {
    int d = (blockIdx.x * blockDim.x + threadIdx.x) >> 5;
    int lane = threadIdx.x & 31;
    if (d >= N) return;
    int e2 = lane >> 1;
    int f = lane & 1;
    int cnt = g_cnt[d];
    float dv = rsqrtf((float)cnt + 1.0f);
    if (cnt > CAP) cnt = CAP;
    const int* row = g_bkt + (size_t)d * CAP;
    float acc = 0.0f;
    int base = 0;
    while (base < cnt) {
        int m = min(16, cnt - base);
        int sid = (lane < m) ? __ldg(row + base + lane) : 0;
        int s = __shfl_sync(0xffffffffu, sid, e2);
        if (e2 < m) acc += __ldg(g_buf1 + (size_t)s * F3 + f);
        base += 16;
    }
    // self term, added once per feature (lanes 0 and 1 only)
    if (lane < 2) acc += g_buf1[(size_t)d * F3 + lane];
#pragma unroll
    for (int off = 2; off < 32; off <<= 1)
        acc += __shfl_xor_sync(0xffffffffu, acc, off);
    float a = fmaf(acc, dv, __ldg(b3 + f));
    float o = __shfl_xor_sync(0xffffffffu, a, 1);
    if (lane < 2) {
        float m = fmaxf(a, o);
        float l = m + logf(expf(a - m) + expf(o - m));
        out[(size_t)d * 2 + lane] = a - l;
    }
}

// ---------------------------------------------------------------------------
extern "C" void kernel_launch(void* const* d_in, const int* in_sizes, int n_in,
                              void* d_out, int out_size) {
    const float* x  = (const float*)d_in[0];
    const int*   ei = (const int*)d_in[1];
    const float* W1 = (const float*)d_in[2];
    const float* b1 = (const float*)d_in[3];
    const float* W2 = (const float*)d_in[4];
    const float* b2 = (const float*)d_in[5];
    const float* W3 = (const float*)d_in[6];
    const float* b3 = (const float*)d_in[7];
    float* out      = (float*)d_out;

    int N = in_sizes[0] / D0;
    int E = in_sizes[1] / 2;
    if (N > NMAX) N = NMAX;
    if (E > EMAX) E = EMAX;

    // Zero degree counters via async memset (capturable)
    void* cnt_ptr = nullptr;
    cudaGetSymbolAddress(&cnt_ptr, g_cnt);
    cudaMemsetAsync(cnt_ptr, 0, (size_t)N * sizeof(int));

    // Fused fill + gemm1 (independent workloads co-scheduled), then dinv scale
    int gb = (((N + 3) / 4) * 32 + 255) / 256;   // gemm1 blocks
    int fb = (E / 4 + 255) / 256;                // fill blocks
    k_fill_gemm1<<<gb + fb, 256>>>(ei, x, W1, E, N, gb, fb);
    k_scale<<<(N * (F1 / 2) + 255) / 256, 256>>>(N);

    // Fused layers
    k_agg1g2<<<(N * 32 + 255) / 256, 256>>>(W2, b1, N);
    k_agg2g3<<<(N * 16 + 255) / 256, 256>>>(W3, b2, N);
    k_agg3<<<(N * 32 + 255) / 256, 256>>>(b3, out, N);
}